// round 10
// baseline (speedup 1.0000x reference)
#include <cuda_runtime.h>
#include <math_constants.h>

// out[c] = dequant(quant(x[c])); group membership permuted by perm.
// Block = 2 rows. Values staged interleaved (s2[c] = {r0[c], r1[c]}) with an
// XOR bank swizzle. Warp w gathers permuted group w (sorted indices ->
// ~conflict-free LDS.64), reduces min/max, quantizes IN REGISTERS (params
// never leave the warp -> no tables), scatters results to a second buffer,
// then all threads reread linearly and store STG.128. inv[] is unused.

#define ROW_C 4096
#define NT    1024
#define Q_MAX 15.0f
#define EPS   1e-5f

__device__ int g_sperm[ROW_C];

__device__ __forceinline__ int swz(int i) { return i ^ ((i >> 4) & 15); }

// One warp per group; closed-form bank-dispersal over 16 bins / 8 cells.
// Element with swizzled residue r, rank k<8 -> pos k*16+((r-k)&15);
// overflow ranks fill the exact complement holes. Within-bin order is
// nondeterministic but min/max reduction cannot observe it.
__global__ void sort_perm_kernel(const int* __restrict__ perm)
{
    __shared__ int emit [32][128];
    __shared__ int holes[32][128];
    __shared__ int cnt[32][16], rk[32][16];
    __shared__ int nhole[32], nov[32];

    const int w    = threadIdx.x >> 5;
    const int lane = threadIdx.x & 31;

    if (lane < 16) { cnt[w][lane] = 0; rk[w][lane] = 0; }
    if (lane == 0) { nhole[w] = 0; nov[w] = 0; }
    __syncwarp();

    int v[4];
    #pragma unroll
    for (int i = 0; i < 4; ++i) {
        v[i] = perm[w * 128 + i * 32 + lane];            // coalesced
        atomicAdd(&cnt[w][swz(v[i]) & 15], 1);
    }
    __syncwarp();

    // hole: p=c*16+s unfilled iff bin (s+c)&15 has cnt <= c
    #pragma unroll
    for (int i = 0; i < 4; ++i) {
        const int p = i * 32 + lane;
        const int c = p >> 4, s = p & 15;
        if (cnt[w][(s + c) & 15] <= c)
            holes[w][atomicAdd(&nhole[w], 1)] = p;
    }
    __syncwarp();

    #pragma unroll
    for (int i = 0; i < 4; ++i) {
        const int r = swz(v[i]) & 15;
        const int k = atomicAdd(&rk[w][r], 1);
        const int pos = (k < 8) ? (k * 16 + ((r - k) & 15))
                                : holes[w][atomicAdd(&nov[w], 1)];
        emit[w][pos] = v[i];
    }
    __syncwarp();

    #pragma unroll
    for (int i = 0; i < 4; ++i)
        g_sperm[w * 128 + i * 32 + lane] = emit[w][i * 32 + lane];
}

extern __shared__ float2 smem_dyn2[];

__global__ __launch_bounds__(NT, 2)
void tpq_kernel(const float* __restrict__ x,
                float*       __restrict__ out)
{
    float2* s2 = smem_dyn2;              // [4096] staged values   (32 KB)
    float2* so = s2 + ROW_C;             // [4096] quantized out   (32 KB)

    const int t    = threadIdx.x;
    const int warp = t >> 5;
    const int lane = t & 31;
    const size_t rowbase = (size_t)blockIdx.x * (2 * ROW_C);

    // ---- 2 x LDG.128: rows r0,r1, channels 4t..4t+3 ----
    const float4 a0 = __ldcs((const float4*)(x + rowbase) + t);
    const float4 a1 = __ldcs((const float4*)(x + rowbase + ROW_C) + t);

    int pp[4];                           // bank-dispersed gather indices
    #pragma unroll
    for (int i = 0; i < 4; ++i)
        pp[i] = g_sperm[warp * 128 + i * 32 + lane];

    // ---- stage interleaved {r0,r1}, swizzled (conflict-free) ----
    const float* a0p = (const float*)&a0;
    const float* a1p = (const float*)&a1;
    #pragma unroll
    for (int j = 0; j < 4; ++j)
        s2[swz(4 * t + j)] = make_float2(a0p[j], a1p[j]);
    __syncthreads();

    // ---- gather permuted group w (both rows per LDS.64) + reduce ----
    float2 v[4];
    float mn0 =  CUDART_INF_F, mx0 = -CUDART_INF_F;
    float mn1 =  CUDART_INF_F, mx1 = -CUDART_INF_F;
    #pragma unroll
    for (int i = 0; i < 4; ++i) {
        v[i] = s2[swz(pp[i])];
        mn0 = fminf(mn0, v[i].x);  mx0 = fmaxf(mx0, v[i].x);
        mn1 = fminf(mn1, v[i].y);  mx1 = fmaxf(mx1, v[i].y);
    }
    #pragma unroll
    for (int off = 16; off; off >>= 1) {
        mn0 = fminf(mn0, __shfl_xor_sync(0xffffffffu, mn0, off));
        mx0 = fmaxf(mx0, __shfl_xor_sync(0xffffffffu, mx0, off));
        mn1 = fminf(mn1, __shfl_xor_sync(0xffffffffu, mn1, off));
        mx1 = fmaxf(mx1, __shfl_xor_sync(0xffffffffu, mx1, off));
    }

    // params in registers, uniform across the warp (exact reference math)
    const float sc0 = fmaxf(mx0 - mn0, EPS) / Q_MAX;
    const float is0 = 1.0f / sc0;
    const float b0  = fminf(fmaxf(rintf(-mn0 / sc0), 0.0f), Q_MAX);
    const float sc1 = fmaxf(mx1 - mn1, EPS) / Q_MAX;
    const float is1 = 1.0f / sc1;
    const float b1  = fminf(fmaxf(rintf(-mn1 / sc1), 0.0f), Q_MAX);

    // ---- quantize in registers, scatter to so (same sorted pattern) ----
    #pragma unroll
    for (int i = 0; i < 4; ++i) {
        float q0 = rintf(v[i].x * is0);
        q0 = fminf(fmaxf(q0, -b0), Q_MAX - b0);          // clip(q+b,0,15)-b
        float q1 = rintf(v[i].y * is1);
        q1 = fminf(fmaxf(q1, -b1), Q_MAX - b1);
        so[swz(pp[i])] = make_float2(q0 * sc0, q1 * sc1);
    }
    __syncthreads();

    // ---- linear reread (conflict-free) + 2 x STG.128 ----
    float4 o0, o1;
    float* o0p = (float*)&o0;
    float* o1p = (float*)&o1;
    #pragma unroll
    for (int j = 0; j < 4; ++j) {
        const float2 w2 = so[swz(4 * t + j)];
        o0p[j] = w2.x;
        o1p[j] = w2.y;
    }
    __stcg((float4*)(out + rowbase) + t,         o0);
    __stcg((float4*)(out + rowbase + ROW_C) + t, o1);
}

extern "C" void kernel_launch(void* const* d_in, const int* in_sizes, int n_in,
                              void* d_out, int out_size)
{
    const float* x    = (const float*)d_in[0];
    const int*   perm = (const int*)d_in[1];
    float*       out  = (float*)d_out;

    sort_perm_kernel<<<1, NT>>>(perm);

    const int smem_bytes = 2 * ROW_C * sizeof(float2);   // 64 KB
    cudaFuncSetAttribute(tpq_kernel,
                         cudaFuncAttributeMaxDynamicSharedMemorySize, smem_bytes);

    const int rows = in_sizes[0] / ROW_C;                // 16384
    tpq_kernel<<<rows / 2, NT, smem_bytes>>>(x, out);
}